// round 8
// baseline (speedup 1.0000x reference)
#include <cuda_runtime.h>
#include <cstdint>

#define S_DIM 16
#define M_DIM 768
#define N_DIM 1024
#define ROWS_PER_BLK 4
#define STAGE_ROWS 6              // ybase-1 .. ybase+4
#define LPAD 68                   // covers x0 >= -65; LPAD*4 = 272 B (16B multiple)
#define RPAD 4
#define RSTRIDE (LPAD + N_DIM + RPAD)   // 1096 floats = 4384 B (16B multiple)
#define ROW_BYTES (N_DIM * 4)     // 4096
#define INVALID_VAL 100.0f

__device__ __forceinline__ uint32_t smem_u32(const void* p) {
    return (uint32_t)__cvta_generic_to_shared(p);
}

__global__ __launch_bounds__(256, 4) void lr_distance_kernel(
    const float* __restrict__ lr,
    const float* __restrict__ rl,
    float* __restrict__ out)
{
    __shared__ __align__(16) float sm[STAGE_ROWS * RSTRIDE];   // 26304 B
    __shared__ __align__(8)  uint64_t mbar;

    const int tid   = threadIdx.x;
    const int bid   = blockIdx.x;
    const int s     = bid / (M_DIM / ROWS_PER_BLK);
    const int grp   = bid % (M_DIM / ROWS_PER_BLK);
    const int ybase = grp * ROWS_PER_BLK;
    const int g0    = ybase - 1;                 // first staged global row

    const float* __restrict__ img = rl + s * (M_DIM * N_DIM);
    const uint32_t bar = smem_u32(&mbar);

    if (tid == 0) {
        asm volatile("mbarrier.init.shared.b64 [%0], %1;" :: "r"(bar), "r"(1) : "memory");
    }
    __syncthreads();

    // Thread 0: one bulk L2->SMEM copy per in-bounds row (TMA path, off the L1 pipe)
    if (tid == 0) {
        int n_valid = 0;
        #pragma unroll
        for (int r = 0; r < STAGE_ROWS; r++) {
            int g = g0 + r;
            if (g >= 0 && g < M_DIM) n_valid++;
        }
        asm volatile("mbarrier.arrive.expect_tx.shared.b64 _, [%0], %1;"
                     :: "r"(bar), "r"(n_valid * ROW_BYTES) : "memory");
        #pragma unroll
        for (int r = 0; r < STAGE_ROWS; r++) {
            int g = g0 + r;
            if (g >= 0 && g < M_DIM) {
                uint32_t dst = smem_u32(sm + r * RSTRIDE + LPAD);
                const float* src = img + g * N_DIM;
                asm volatile(
                    "cp.async.bulk.shared::cta.global.mbarrier::complete_tx::bytes "
                    "[%0], [%1], %2, [%3];"
                    :: "r"(dst), "l"(src), "r"(ROW_BYTES), "r"(bar) : "memory");
            }
        }
    }

    // Meanwhile: zero the pads (72 floats/row, disjoint from TMA destinations)
    for (int v = tid; v < STAGE_ROWS * (LPAD + RPAD); v += 256) {
        int r = v / (LPAD + RPAD);
        int p = v % (LPAD + RPAD);
        int idx = (p < LPAD) ? p : (LPAD + N_DIM + (p - LPAD));
        sm[r * RSTRIDE + idx] = 0.0f;
    }
    // ...and zero out-of-bounds rows (only first/last block of each image)
    #pragma unroll
    for (int r = 0; r < STAGE_ROWS; r++) {
        int g = g0 + r;
        if (g < 0 || g >= M_DIM) {
            for (int c = tid; c < N_DIM / 4; c += 256)
                reinterpret_cast<float4*>(sm + r * RSTRIDE + LPAD)[c] =
                    make_float4(0.0f, 0.0f, 0.0f, 0.0f);
        }
    }
    __syncthreads();

    // Wait for the bulk copies (acquire orders subsequent LDS after TMA writes)
    {
        uint32_t done;
        do {
            asm volatile(
                "{\n\t.reg .pred p;\n\t"
                "mbarrier.try_wait.parity.acquire.cta.shared::cta.b64 p, [%1], %2;\n\t"
                "selp.b32 %0, 1, 0, p;\n\t}"
                : "=r"(done) : "r"(bar), "r"(0u) : "memory");
        } while (!done);
    }

    const int   xs    = tid * 4;
    const float xlb   = (float)xs;
    const int   sbase = s * (M_DIM * N_DIM);

    // ix = ((2*xr/1023 - 1 + 1)*1024 - 1)/2  ==  fma(fma(xr, 2/1023, -1), 512, 511.5)
    const float RCP_SCALE = 2.0f / 1023.0f;

    #pragma unroll
    for (int r = 0; r < ROWS_PER_BLK; r++) {
        const int y = ybase + r;

        // Vertical terms (reference formula chain), once per row
        float yl  = 2.0f * (float)y / (float)(M_DIM - 1) - 1.0f;
        float iy  = ((yl + 1.0f) * (float)M_DIM - 1.0f) * 0.5f;
        float y0f = floorf(iy);
        float wy1 = iy - y0f;
        float wy0 = 1.0f - wy1;
        int   r0  = (int)y0f - g0;                 // staged row index, in [0,4]
        const float* __restrict__ rowb = sm + r0 * RSTRIDE;

        float4 dv = *reinterpret_cast<const float4*>(lr + sbase + y * N_DIM + xs);
        float dd[4] = {dv.x, dv.y, dv.z, dv.w};

        // Phase 1: all addresses + weights
        int   idx[4];
        float wx1[4], xr[4];
        #pragma unroll
        for (int j = 0; j < 4; j++) {
            xr[j]     = (xlb + (float)j) - dd[j];
            float t   = fmaf(xr[j], RCP_SCALE, -1.0f);
            float ix  = fmaf(t, 512.0f, 511.5f);
            float x0f = floorf(ix);
            wx1[j]    = ix - x0f;
            idx[j]    = (int)x0f + LPAD;           // provably in [3, 1092]: pads absorb OOB
        }

        // Phase 2: batch all 16 LDS taps (deep MLP hides smem latency)
        float v00[4], v01[4], v10[4], v11[4];
        #pragma unroll
        for (int j = 0; j < 4; j++) {
            v00[j] = rowb[idx[j]];
            v01[j] = rowb[idx[j] + 1];
            v10[j] = rowb[idx[j] + RSTRIDE];
            v11[j] = rowb[idx[j] + RSTRIDE + 1];
        }

        // Phase 3: arithmetic + select
        float res[4];
        #pragma unroll
        for (int j = 0; j < 4; j++) {
            float wx0 = 1.0f - wx1[j];
            float warped = (v00[j] * wx0 + v01[j] * wx1[j]) * wy0
                         + (v10[j] * wx0 + v11[j] * wx1[j]) * wy1;
            float dist = fabsf(dd[j] + warped);
            bool invalid = (xr[j] < 0.0f) || (xr[j] >= (float)N_DIM);
            res[j] = invalid ? INVALID_VAL : dist;
        }

        *reinterpret_cast<float4*>(out + sbase + y * N_DIM + xs) =
            make_float4(res[0], res[1], res[2], res[3]);
    }
}

extern "C" void kernel_launch(void* const* d_in, const int* in_sizes, int n_in,
                              void* d_out, int out_size)
{
    const float* lr = (const float*)d_in[0];
    const float* rl = (const float*)d_in[1];
    float* out = (float*)d_out;

    int blocks = S_DIM * (M_DIM / ROWS_PER_BLK);   // 3072
    lr_distance_kernel<<<blocks, 256>>>(lr, rl, out);
}

// round 9
// speedup vs baseline: 1.1188x; 1.1188x over previous
#include <cuda_runtime.h>
#include <cstdint>

#define S_DIM 16
#define M_DIM 768
#define N_DIM 1024
#define ROWS_PER_BLK 2
#define STAGE_ROWS 4              // ybase-1 .. ybase+2
#define LPAD 68                   // covers x0 >= -65; LPAD*4 = 272 B (16B multiple)
#define RPAD 4
#define RSTRIDE (LPAD + N_DIM + RPAD)   // 1096 floats = 4384 B (16B multiple)
#define ROW_BYTES (N_DIM * 4)     // 4096
#define BL_OFF (STAGE_ROWS * RSTRIDE)   // blend buffer base (floats)
#define VEC_PER_ROW (RSTRIDE / 4)       // 274 float4 per padded row
#define INVALID_VAL 100.0f

__device__ __forceinline__ uint32_t smem_u32(const void* p) {
    return (uint32_t)__cvta_generic_to_shared(p);
}

__global__ __launch_bounds__(256) void lr_distance_kernel(
    const float* __restrict__ lr,
    const float* __restrict__ rl,
    float* __restrict__ out)
{
    // 4 staged rows + 2 blended rows = 6 * 4384 B = 26304 B (same as R7)
    __shared__ __align__(16) float sm[(STAGE_ROWS + ROWS_PER_BLK) * RSTRIDE];
    __shared__ __align__(8)  uint64_t mbar;

    const int tid   = threadIdx.x;
    const int bid   = blockIdx.x;
    const int s     = bid / (M_DIM / ROWS_PER_BLK);
    const int grp   = bid % (M_DIM / ROWS_PER_BLK);
    const int ybase = grp * ROWS_PER_BLK;
    const int g0    = ybase - 1;                 // first staged global row

    const float* __restrict__ img = rl + s * (M_DIM * N_DIM);
    const uint32_t bar = smem_u32(&mbar);

    if (tid == 0) {
        asm volatile("mbarrier.init.shared.b64 [%0], %1;" :: "r"(bar), "r"(1) : "memory");
    }
    __syncthreads();

    // Thread 0: one bulk L2->SMEM copy per in-bounds staged row (TMA path)
    if (tid == 0) {
        int n_valid = 0;
        #pragma unroll
        for (int r = 0; r < STAGE_ROWS; r++) {
            int g = g0 + r;
            if (g >= 0 && g < M_DIM) n_valid++;
        }
        asm volatile("mbarrier.arrive.expect_tx.shared.b64 _, [%0], %1;"
                     :: "r"(bar), "r"(n_valid * ROW_BYTES) : "memory");
        #pragma unroll
        for (int r = 0; r < STAGE_ROWS; r++) {
            int g = g0 + r;
            if (g >= 0 && g < M_DIM) {
                uint32_t dst = smem_u32(sm + r * RSTRIDE + LPAD);
                const float* src = img + g * N_DIM;
                asm volatile(
                    "cp.async.bulk.shared::cta.global.mbarrier::complete_tx::bytes "
                    "[%0], [%1], %2, [%3];"
                    :: "r"(dst), "l"(src), "r"(ROW_BYTES), "r"(bar) : "memory");
            }
        }
    }

    // Zero staged-row pads (72 floats/row, disjoint from TMA destinations)
    for (int v = tid; v < STAGE_ROWS * (LPAD + RPAD); v += 256) {
        int r = v / (LPAD + RPAD);
        int p = v % (LPAD + RPAD);
        int idx = (p < LPAD) ? p : (LPAD + N_DIM + (p - LPAD));
        sm[r * RSTRIDE + idx] = 0.0f;
    }
    // Zero out-of-bounds staged rows (first/last block of each image only)
    #pragma unroll
    for (int r = 0; r < STAGE_ROWS; r++) {
        int g = g0 + r;
        if (g < 0 || g >= M_DIM) {
            for (int c = tid; c < N_DIM / 4; c += 256)
                reinterpret_cast<float4*>(sm + r * RSTRIDE + LPAD)[c] =
                    make_float4(0.0f, 0.0f, 0.0f, 0.0f);
        }
    }
    __syncthreads();   // pad/OOB stores visible

    // Wait for the bulk copies (acquire orders subsequent LDS after TMA writes)
    {
        uint32_t done;
        do {
            asm volatile(
                "{\n\t.reg .pred p;\n\t"
                "mbarrier.try_wait.parity.acquire.cta.shared::cta.b64 p, [%1], %2;\n\t"
                "selp.b32 %0, 1, 0, p;\n\t}"
                : "=r"(done) : "r"(bar), "r"(0u) : "memory");
        } while (!done);
    }

    // ── Vertical pre-blend: one padded row per output row, fully vectorized ──
    #pragma unroll
    for (int r = 0; r < ROWS_PER_BLK; r++) {
        const int y = ybase + r;
        float yl  = 2.0f * (float)y / (float)(M_DIM - 1) - 1.0f;
        float iy  = ((yl + 1.0f) * (float)M_DIM - 1.0f) * 0.5f;
        float y0f = floorf(iy);
        float wy1 = iy - y0f;
        int   r0  = (int)y0f - g0;               // in [0, 2]

        const float4* __restrict__ a = reinterpret_cast<const float4*>(sm + r0 * RSTRIDE);
        const float4* __restrict__ b = reinterpret_cast<const float4*>(sm + (r0 + 1) * RSTRIDE);
        float4* __restrict__ dst = reinterpret_cast<float4*>(sm + BL_OFF + r * RSTRIDE);

        for (int c = tid; c < VEC_PER_ROW; c += 256) {
            float4 va = a[c], vb = b[c], o;
            o.x = fmaf(wy1, vb.x - va.x, va.x);
            o.y = fmaf(wy1, vb.y - va.y, va.y);
            o.z = fmaf(wy1, vb.z - va.z, va.z);
            o.w = fmaf(wy1, vb.w - va.w, va.w);
            dst[c] = o;
        }
    }
    __syncthreads();

    // ── Gather: 2 random taps per element from the blended row ──
    const int   xs    = tid * 4;
    const float xlb   = (float)xs;
    const int   sbase = s * (M_DIM * N_DIM);
    const float RCP_SCALE = 2.0f / 1023.0f;

    #pragma unroll
    for (int r = 0; r < ROWS_PER_BLK; r++) {
        const int y = ybase + r;
        const float* __restrict__ rowb = sm + BL_OFF + r * RSTRIDE;

        float4 dv = *reinterpret_cast<const float4*>(lr + sbase + y * N_DIM + xs);
        float dd[4] = {dv.x, dv.y, dv.z, dv.w};
        float res[4];

        #pragma unroll
        for (int j = 0; j < 4; j++) {
            float d  = dd[j];
            float xr = (xlb + (float)j) - d;

            float t   = fmaf(xr, RCP_SCALE, -1.0f);   // xr_normed
            float ix  = fmaf(t, 512.0f, 511.5f);      // ((t+1)*1024 - 1)*0.5
            float x0f = floorf(ix);
            float wx1 = ix - x0f;
            int   idx = (int)x0f + LPAD;              // in [3, 1092]; pads absorb OOB

            float b0 = rowb[idx];
            float b1 = rowb[idx + 1];
            float warped = fmaf(wx1, b1 - b0, b0);

            float dist = fabsf(d + warped);
            bool invalid = (xr < 0.0f) || (xr >= (float)N_DIM);
            res[j] = invalid ? INVALID_VAL : dist;
        }

        *reinterpret_cast<float4*>(out + sbase + y * N_DIM + xs) =
            make_float4(res[0], res[1], res[2], res[3]);
    }
}

extern "C" void kernel_launch(void* const* d_in, const int* in_sizes, int n_in,
                              void* d_out, int out_size)
{
    const float* lr = (const float*)d_in[0];
    const float* rl = (const float*)d_in[1];
    float* out = (float*)d_out;

    int blocks = S_DIM * (M_DIM / ROWS_PER_BLK);   // 16 * 384 = 6144
    lr_distance_kernel<<<blocks, 256>>>(lr, rl, out);
}

// round 10
// speedup vs baseline: 1.2097x; 1.0812x over previous
#include <cuda_runtime.h>
#include <cstdint>

#define S_DIM 16
#define M_DIM 768
#define N_DIM 1024
#define ROWS_PER_BLK 2
#define STAGE_ROWS 3              // exactly y0(ybase) .. y0(ybase+1)+1
#define LPAD 68                   // covers x0 >= -65; LPAD*4 = 272 B (16B multiple)
#define RPAD 4
#define RSTRIDE (LPAD + N_DIM + RPAD)   // 1096 floats = 4384 B (16B multiple)
#define ROW_BYTES (N_DIM * 4)     // 4096
#define BL_OFF (STAGE_ROWS * RSTRIDE)   // blend buffer base (floats)
#define VEC_PER_ROW (RSTRIDE / 4)       // 274 float4 per padded row
#define INVALID_VAL 100.0f

__device__ __forceinline__ uint32_t smem_u32(const void* p) {
    return (uint32_t)__cvta_generic_to_shared(p);
}

__global__ __launch_bounds__(256) void lr_distance_kernel(
    const float* __restrict__ lr,
    const float* __restrict__ rl,
    float* __restrict__ out)
{
    // 3 staged rows + 2 blended rows = 5 * 4384 B = 21920 B
    __shared__ __align__(16) float sm[(STAGE_ROWS + ROWS_PER_BLK) * RSTRIDE];
    __shared__ __align__(8)  uint64_t mbar;

    const int tid   = threadIdx.x;
    const int bid   = blockIdx.x;
    const int s     = bid / (M_DIM / ROWS_PER_BLK);
    const int grp   = bid % (M_DIM / ROWS_PER_BLK);
    const int ybase = grp * ROWS_PER_BLK;
    // y0(y) = y-1 for y <= M/2-1, y for y >= M/2  (iy = y*M/(M-1) - 0.5)
    const int g0    = ybase - (ybase < (M_DIM / 2) ? 1 : 0);  // first staged row

    const float* __restrict__ img = rl + s * (M_DIM * N_DIM);
    const uint32_t bar = smem_u32(&mbar);

    if (tid == 0) {
        asm volatile("mbarrier.init.shared.b64 [%0], %1;" :: "r"(bar), "r"(1) : "memory");
    }
    __syncthreads();

    // Thread 0: one bulk L2->SMEM copy per in-bounds staged row (TMA path)
    if (tid == 0) {
        int n_valid = 0;
        #pragma unroll
        for (int r = 0; r < STAGE_ROWS; r++) {
            int g = g0 + r;
            if (g >= 0 && g < M_DIM) n_valid++;
        }
        asm volatile("mbarrier.arrive.expect_tx.shared.b64 _, [%0], %1;"
                     :: "r"(bar), "r"(n_valid * ROW_BYTES) : "memory");
        #pragma unroll
        for (int r = 0; r < STAGE_ROWS; r++) {
            int g = g0 + r;
            if (g >= 0 && g < M_DIM) {
                uint32_t dst = smem_u32(sm + r * RSTRIDE + LPAD);
                const float* src = img + g * N_DIM;
                asm volatile(
                    "cp.async.bulk.shared::cta.global.mbarrier::complete_tx::bytes "
                    "[%0], [%1], %2, [%3];"
                    :: "r"(dst), "l"(src), "r"(ROW_BYTES), "r"(bar) : "memory");
            }
        }
    }

    // Zero staged-row pads (72 floats/row, disjoint from TMA destinations)
    for (int v = tid; v < STAGE_ROWS * (LPAD + RPAD); v += 256) {
        int r = v / (LPAD + RPAD);
        int p = v % (LPAD + RPAD);
        int idx = (p < LPAD) ? p : (LPAD + N_DIM + (p - LPAD));
        sm[r * RSTRIDE + idx] = 0.0f;
    }
    // Zero out-of-bounds staged rows (only first/last group of each image)
    #pragma unroll
    for (int r = 0; r < STAGE_ROWS; r++) {
        int g = g0 + r;
        if (g < 0 || g >= M_DIM) {
            for (int c = tid; c < N_DIM / 4; c += 256)
                reinterpret_cast<float4*>(sm + r * RSTRIDE + LPAD)[c] =
                    make_float4(0.0f, 0.0f, 0.0f, 0.0f);
        }
    }
    __syncthreads();   // pad/OOB stores visible

    // Wait for the bulk copies (acquire orders subsequent LDS after TMA writes)
    {
        uint32_t done;
        do {
            asm volatile(
                "{\n\t.reg .pred p;\n\t"
                "mbarrier.try_wait.parity.acquire.cta.shared::cta.b64 p, [%1], %2;\n\t"
                "selp.b32 %0, 1, 0, p;\n\t}"
                : "=r"(done) : "r"(bar), "r"(0u) : "memory");
        } while (!done);
    }

    // ── Vertical pre-blend: one padded row per output row, fully vectorized ──
    #pragma unroll
    for (int r = 0; r < ROWS_PER_BLK; r++) {
        const int y = ybase + r;
        float yl  = 2.0f * (float)y / (float)(M_DIM - 1) - 1.0f;
        float iy  = ((yl + 1.0f) * (float)M_DIM - 1.0f) * 0.5f;
        float y0f = floorf(iy);
        float wy1 = iy - y0f;
        int   r0  = (int)y0f - g0;               // in [0, 1]

        const float4* __restrict__ a = reinterpret_cast<const float4*>(sm + r0 * RSTRIDE);
        const float4* __restrict__ b = reinterpret_cast<const float4*>(sm + (r0 + 1) * RSTRIDE);
        float4* __restrict__ dst = reinterpret_cast<float4*>(sm + BL_OFF + r * RSTRIDE);

        for (int c = tid; c < VEC_PER_ROW; c += 256) {
            float4 va = a[c], vb = b[c], o;
            o.x = fmaf(wy1, vb.x - va.x, va.x);
            o.y = fmaf(wy1, vb.y - va.y, va.y);
            o.z = fmaf(wy1, vb.z - va.z, va.z);
            o.w = fmaf(wy1, vb.w - va.w, va.w);
            dst[c] = o;
        }
    }
    __syncthreads();

    // ── Gather: 2 random taps per element from the blended row ──
    const int   xs    = tid * 4;
    const float xlb   = (float)xs;
    const int   sbase = s * (M_DIM * N_DIM);
    const float RCP_SCALE = 2.0f / 1023.0f;

    #pragma unroll
    for (int r = 0; r < ROWS_PER_BLK; r++) {
        const int y = ybase + r;
        const float* __restrict__ rowb = sm + BL_OFF + r * RSTRIDE;

        float4 dv = *reinterpret_cast<const float4*>(lr + sbase + y * N_DIM + xs);
        float dd[4] = {dv.x, dv.y, dv.z, dv.w};
        float res[4];

        #pragma unroll
        for (int j = 0; j < 4; j++) {
            float d  = dd[j];
            float xr = (xlb + (float)j) - d;

            float t   = fmaf(xr, RCP_SCALE, -1.0f);   // xr_normed
            float ix  = fmaf(t, 512.0f, 511.5f);      // ((t+1)*1024 - 1)*0.5
            float x0f = floorf(ix);
            float wx1 = ix - x0f;
            int   idx = (int)x0f + LPAD;              // in [3, 1092]; pads absorb OOB

            float b0 = rowb[idx];
            float b1 = rowb[idx + 1];
            float warped = fmaf(wx1, b1 - b0, b0);

            float dist = fabsf(d + warped);
            bool invalid = (xr < 0.0f) || (xr >= (float)N_DIM);
            res[j] = invalid ? INVALID_VAL : dist;
        }

        *reinterpret_cast<float4*>(out + sbase + y * N_DIM + xs) =
            make_float4(res[0], res[1], res[2], res[3]);
    }
}

extern "C" void kernel_launch(void* const* d_in, const int* in_sizes, int n_in,
                              void* d_out, int out_size)
{
    const float* lr = (const float*)d_in[0];
    const float* rl = (const float*)d_in[1];
    float* out = (float*)d_out;

    int blocks = S_DIM * (M_DIM / ROWS_PER_BLK);   // 16 * 384 = 6144
    lr_distance_kernel<<<blocks, 256>>>(lr, rl, out);
}